// round 2
// baseline (speedup 1.0000x reference)
#include <cuda_runtime.h>
#include <cstdint>

#define FN 92
#define FE 64
#define HD 128
#define NG 256
#define LAYERS 3
#define MAXN 50000
#define MAXE 800000

// ---------------- scratch (static device allocations) ----------------
__device__ float d_h[MAXN * HD];        // node features
__device__ float d_S[MAXN * HD];        // gather-sum  S = A * h
__device__ float d_EA[MAXN * FE];       // segsum(edge_attr, row)  (layer-invariant)
__device__ float d_deginv[MAXN];
__device__ int   d_cnt[MAXN];
__device__ int   d_cur[MAXN];
__device__ int   d_off[MAXN + 1];
__device__ int   d_perm[MAXE];          // edge id, bucketed by row
__device__ int   d_colp[MAXE];          // col[perm[j]] pre-resolved
__device__ float d_gpool[NG * HD];

// ---------------- CSR build ----------------
__global__ void k_zero(int n) {
    int i = blockIdx.x * blockDim.x + threadIdx.x;
    if (i < n) { d_cnt[i] = 0; d_cur[i] = 0; }
}

__global__ void k_hist(const int* __restrict__ row, int e) {
    int i = blockIdx.x * blockDim.x + threadIdx.x;
    if (i < e) atomicAdd(&d_cnt[__ldg(row + i)], 1);
}

// single-block exclusive scan over counts -> offsets, also deg_inv
__global__ void k_scan(int n) {
    __shared__ int wsum[32];
    __shared__ int s_carry, s_total;
    int t = threadIdx.x, lane = t & 31, w = t >> 5;
    if (t == 0) s_carry = 0;
    __syncthreads();
    for (int base = 0; base < n; base += 1024) {
        int i = base + t;
        int v = (i < n) ? d_cnt[i] : 0;
        int x = v;
        #pragma unroll
        for (int s = 1; s < 32; s <<= 1) {
            int y = __shfl_up_sync(0xffffffffu, x, s);
            if (lane >= s) x += y;
        }
        if (lane == 31) wsum[w] = x;
        __syncthreads();
        if (w == 0) {
            int y = wsum[lane];
            int z = y;
            #pragma unroll
            for (int s = 1; s < 32; s <<= 1) {
                int q = __shfl_up_sync(0xffffffffu, z, s);
                if (lane >= s) z += q;
            }
            if (lane == 31) s_total = z;
            wsum[lane] = z - y;   // exclusive warp offsets
        }
        __syncthreads();
        if (i < n) {
            d_off[i] = s_carry + wsum[w] + (x - v);
            d_deginv[i] = 1.0f / fmaxf((float)v, 1.0f);
        }
        __syncthreads();
        if (t == 0) s_carry += s_total;
        __syncthreads();
    }
    if (t == 0) d_off[n] = s_carry;
}

__global__ void k_scatter(const int* __restrict__ row, const int* __restrict__ col, int e) {
    int i = blockIdx.x * blockDim.x + threadIdx.x;
    if (i >= e) return;
    int r = __ldg(row + i);
    int pos = atomicAdd(&d_cur[r], 1);
    int idx = d_off[r] + pos;
    d_perm[idx] = i;
    d_colp[idx] = __ldg(col + i);
}

// ---------------- EA = segsum(edge_attr, row)  (warp per node) ----------------
__global__ void k_ea(const float* __restrict__ ea, int n) {
    int gw = (blockIdx.x * blockDim.x + threadIdx.x) >> 5;
    int lane = threadIdx.x & 31;
    if (gw >= n) return;
    int s = d_off[gw], e = d_off[gw + 1];
    float2 acc = make_float2(0.f, 0.f);
    #pragma unroll 4
    for (int j = s; j < e; ++j) {
        int eid = d_perm[j];
        float2 v = __ldg((const float2*)(ea + (size_t)eid * FE + lane * 2));
        acc.x += v.x; acc.y += v.y;
    }
    *(float2*)(d_EA + (size_t)gw * FE + lane * 2) = acc;
}

// ---------------- SpMM gather-sum: S[i] = sum_{e in CSR(i)} h[col[e]] ----------------
__global__ void k_spmm(int n) {
    int gw = (blockIdx.x * blockDim.x + threadIdx.x) >> 5;
    int lane = threadIdx.x & 31;
    if (gw >= n) return;
    int s = d_off[gw], e = d_off[gw + 1];
    float4 acc = make_float4(0.f, 0.f, 0.f, 0.f);
    const float4* hp = (const float4*)d_h;
    #pragma unroll 4
    for (int j = s; j < e; ++j) {
        int c = d_colp[j];
        float4 v = hp[(size_t)c * 32 + lane];
        acc.x += v.x; acc.y += v.y; acc.z += v.z; acc.w += v.w;
    }
    ((float4*)d_S)[(size_t)gw * 32 + lane] = acc;
}

// ---------------- unified node GEMM (M tile 64 x full 128 cols) ----------------
// mode 0: h = relu(A1[n,K] @ W + bias)                      (embedding, K=FN)
// mode 1: h += relu(((([S|EA]) @ W) * deginv + bias) * gamma/sqrt(1+eps) + beta)
__global__ void __launch_bounds__(256) k_gemm(
    const float* __restrict__ A1, int K,
    const float* __restrict__ W,
    const float* __restrict__ bias,
    const float* __restrict__ gam,
    const float* __restrict__ bet,
    int mode, int n)
{
    __shared__ float As[64 * 32];
    __shared__ float Ws[32 * 128];
    int tid = threadIdx.x;
    int tc = tid & 31;       // col group: cols tc*4 .. tc*4+3
    int tr = tid >> 5;       // row group: rows tr*8 .. tr*8+7 (uniform per warp)
    int m0 = blockIdx.x * 64;

    float acc[8][4];
    #pragma unroll
    for (int r = 0; r < 8; ++r)
        #pragma unroll
        for (int c = 0; c < 4; ++c) acc[r][c] = 0.f;

    for (int k0 = 0; k0 < K; k0 += 32) {
        // A chunk: 64x32
        #pragma unroll
        for (int i = 0; i < 8; ++i) {
            int idx = tid + i * 256;
            int m = idx >> 5, kk = idx & 31;
            int k = k0 + kk, gm = m0 + m;
            float v = 0.f;
            if (gm < n && k < K) {
                if (mode == 0)      v = A1[(size_t)gm * K + k];
                else if (k < HD)    v = d_S[(size_t)gm * HD + k];
                else                v = d_EA[(size_t)gm * FE + (k - HD)];
            }
            As[idx] = v;
        }
        // W chunk: 32x128
        #pragma unroll
        for (int i = 0; i < 16; ++i) {
            int idx = tid + i * 256;
            int kk = idx >> 7, j = idx & 127;
            int k = k0 + kk;
            Ws[idx] = (k < K) ? W[(size_t)k * 128 + j] : 0.f;
        }
        __syncthreads();
        #pragma unroll
        for (int kk = 0; kk < 32; ++kk) {
            float a[8];
            #pragma unroll
            for (int r = 0; r < 8; ++r) a[r] = As[(tr * 8 + r) * 32 + kk];
            float4 b = *(const float4*)&Ws[kk * 128 + tc * 4];
            #pragma unroll
            for (int r = 0; r < 8; ++r) {
                acc[r][0] += a[r] * b.x;
                acc[r][1] += a[r] * b.y;
                acc[r][2] += a[r] * b.z;
                acc[r][3] += a[r] * b.w;
            }
        }
        __syncthreads();
    }

    const float bnc = rsqrtf(1.0f + 1e-3f);
    #pragma unroll
    for (int r = 0; r < 8; ++r) {
        int gm = m0 + tr * 8 + r;
        if (gm >= n) continue;
        float4* hp = (float4*)&d_h[(size_t)gm * HD + tc * 4];
        if (mode == 0) {
            float4 o;
            o.x = fmaxf(acc[r][0] + bias[tc * 4 + 0], 0.f);
            o.y = fmaxf(acc[r][1] + bias[tc * 4 + 1], 0.f);
            o.z = fmaxf(acc[r][2] + bias[tc * 4 + 2], 0.f);
            o.w = fmaxf(acc[r][3] + bias[tc * 4 + 3], 0.f);
            *hp = o;
        } else {
            float di = d_deginv[gm];
            float4 hv = *hp;
            float* hvp = (float*)&hv;
            #pragma unroll
            for (int c = 0; c < 4; ++c) {
                int j = tc * 4 + c;
                float v = acc[r][c] * di + bias[j];
                v = v * (gam[j] * bnc) + bet[j];
                hvp[c] += fmaxf(v, 0.f);
            }
            *hp = hv;
        }
    }
}

// ---------------- graph mean-pool (batch_idx sorted; block per graph) ----------------
__global__ void k_pool(const int* __restrict__ bidx, int n) {
    int g = blockIdx.x, t = threadIdx.x;   // 128 threads
    int lo, hi;
    { int a = 0, b = n; while (a < b) { int m = (a + b) >> 1; if (bidx[m] < g)     a = m + 1; else b = m; } lo = a; }
    { int a = 0, b = n; while (a < b) { int m = (a + b) >> 1; if (bidx[m] < g + 1) a = m + 1; else b = m; } hi = a; }
    float acc = 0.f;
    for (int i = lo; i < hi; ++i) acc += d_h[(size_t)i * HD + t];
    float inv = 1.0f / fmaxf((float)(hi - lo), 1.0f);
    d_gpool[g * HD + t] = acc * inv;
}

// ---------------- head: relu(g@Wh+bh) @ Wout + bout ----------------
__global__ void k_head(const float* __restrict__ Wh, const float* __restrict__ bh,
                       const float* __restrict__ Wout, const float* __restrict__ bout,
                       float* __restrict__ out) {
    __shared__ float gs[128];
    __shared__ float red[4];
    int g = blockIdx.x, t = threadIdx.x;
    gs[t] = d_gpool[g * HD + t];
    __syncthreads();
    float acc = bh[t];
    #pragma unroll 8
    for (int k = 0; k < 128; ++k) acc += gs[k] * Wh[k * 128 + t];
    float hv = fmaxf(acc, 0.f);
    float p = hv * Wout[t];
    #pragma unroll
    for (int s = 16; s; s >>= 1) p += __shfl_down_sync(0xffffffffu, p, s);
    if ((t & 31) == 0) red[t >> 5] = p;
    __syncthreads();
    if (t == 0) out[g] = red[0] + red[1] + red[2] + red[3] + bout[0];
}

// ---------------- launch ----------------
extern "C" void kernel_launch(void* const* d_in, const int* in_sizes, int n_in,
                              void* d_out, int out_size) {
    const float* x     = (const float*)d_in[0];
    const int*   ei    = (const int*)  d_in[1];
    const float* ea    = (const float*)d_in[2];
    const int*   bidx  = (const int*)  d_in[3];
    const float* W_emb = (const float*)d_in[4];
    const float* b_emb = (const float*)d_in[5];
    const float* Wc    = (const float*)d_in[6];
    const float* bc    = (const float*)d_in[7];
    const float* gamma = (const float*)d_in[8];
    const float* beta  = (const float*)d_in[9];
    const float* Wh    = (const float*)d_in[10];
    const float* bh    = (const float*)d_in[11];
    const float* Wout  = (const float*)d_in[12];
    const float* bout  = (const float*)d_in[13];
    float* out = (float*)d_out;

    int n = in_sizes[0] / FN;
    int e = in_sizes[1] / 2;
    const int* row = ei;
    const int* col = ei + e;

    // CSR build
    k_zero   <<<(n + 255) / 256, 256>>>(n);
    k_hist   <<<(e + 255) / 256, 256>>>(row, e);
    k_scan   <<<1, 1024>>>(n);
    k_scatter<<<(e + 255) / 256, 256>>>(row, col, e);

    // layer-invariant edge-attr aggregation
    k_ea<<<(n * 32 + 255) / 256, 256>>>(ea, n);

    int gb = (n + 63) / 64;
    // embedding: h = relu(x @ W_emb + b_emb)
    k_gemm<<<gb, 256>>>(x, FN, W_emb, b_emb, nullptr, nullptr, 0, n);

    for (int l = 0; l < LAYERS; ++l) {
        k_spmm<<<(n * 32 + 255) / 256, 256>>>(n);
        k_gemm<<<gb, 256>>>(nullptr, HD + FE,
                            Wc + (size_t)l * (HD + FE) * HD,
                            bc + (size_t)l * HD,
                            gamma + (size_t)l * HD,
                            beta + (size_t)l * HD,
                            1, n);
    }

    k_pool<<<NG, 128>>>(bidx, n);
    k_head<<<NG, 128>>>(Wh, bh, Wout, bout, out);
}

// round 3
// speedup vs baseline: 1.2682x; 1.2682x over previous
#include <cuda_runtime.h>
#include <cstdint>

#define FN 92
#define FE 64
#define HD 128
#define KC 192          // HD + FE
#define NG 256
#define LAYERS 3
#define MAXN 50000
#define MAXE 800000

// ---------------- scratch (static device allocations) ----------------
__device__ float d_h[MAXN * HD];          // node features
__device__ float d_SA[MAXN * KC];         // [S | EA] unified A matrix for layer GEMMs
__device__ float d_deginv[MAXN];
__device__ int   d_cnt[MAXN];
__device__ int   d_cur[MAXN];
__device__ int   d_off[MAXN + 1];
__device__ int   d_perm[MAXE];
__device__ int   d_colp[MAXE];
__device__ float d_gpool[NG * HD];

// ---------------- CSR build ----------------
__global__ void k_zero(int n) {
    int i = blockIdx.x * blockDim.x + threadIdx.x;
    if (i < n) { d_cnt[i] = 0; d_cur[i] = 0; }
}

__global__ void k_hist(const int* __restrict__ row, int e) {
    int i = blockIdx.x * blockDim.x + threadIdx.x;
    if (i < e) atomicAdd(&d_cnt[__ldg(row + i)], 1);
}

__global__ void k_scan(int n) {
    __shared__ int wsum[32];
    __shared__ int s_carry, s_total;
    int t = threadIdx.x, lane = t & 31, w = t >> 5;
    if (t == 0) s_carry = 0;
    __syncthreads();
    for (int base = 0; base < n; base += 1024) {
        int i = base + t;
        int v = (i < n) ? d_cnt[i] : 0;
        int x = v;
        #pragma unroll
        for (int s = 1; s < 32; s <<= 1) {
            int y = __shfl_up_sync(0xffffffffu, x, s);
            if (lane >= s) x += y;
        }
        if (lane == 31) wsum[w] = x;
        __syncthreads();
        if (w == 0) {
            int y = wsum[lane];
            int z = y;
            #pragma unroll
            for (int s = 1; s < 32; s <<= 1) {
                int q = __shfl_up_sync(0xffffffffu, z, s);
                if (lane >= s) z += q;
            }
            if (lane == 31) s_total = z;
            wsum[lane] = z - y;
        }
        __syncthreads();
        if (i < n) {
            d_off[i] = s_carry + wsum[w] + (x - v);
            d_deginv[i] = 1.0f / fmaxf((float)v, 1.0f);
        }
        __syncthreads();
        if (t == 0) s_carry += s_total;
        __syncthreads();
    }
    if (t == 0) d_off[n] = s_carry;
}

__global__ void k_scatter(const int* __restrict__ row, const int* __restrict__ col, int e) {
    int i = blockIdx.x * blockDim.x + threadIdx.x;
    if (i >= e) return;
    int r = __ldg(row + i);
    int pos = atomicAdd(&d_cur[r], 1);
    int idx = d_off[r] + pos;
    d_perm[idx] = i;
    d_colp[idx] = __ldg(col + i);
}

// ---------------- EA = segsum(edge_attr, row) -> d_SA cols [128,192) ----------------
__global__ void k_ea(const float* __restrict__ ea, int n) {
    int gw = (blockIdx.x * blockDim.x + threadIdx.x) >> 5;
    int lane = threadIdx.x & 31;
    if (gw >= n) return;
    int s = d_off[gw], e = d_off[gw + 1];
    float2 acc = make_float2(0.f, 0.f);
    #pragma unroll 4
    for (int j = s; j < e; ++j) {
        int eid = d_perm[j];
        float2 v = __ldg((const float2*)(ea + (size_t)eid * FE + lane * 2));
        acc.x += v.x; acc.y += v.y;
    }
    *(float2*)(d_SA + (size_t)gw * KC + HD + lane * 2) = acc;
}

// ---------------- SpMM gather-sum -> d_SA cols [0,128) ----------------
__global__ void k_spmm(int n) {
    int gw = (blockIdx.x * blockDim.x + threadIdx.x) >> 5;
    int lane = threadIdx.x & 31;
    if (gw >= n) return;
    int s = d_off[gw], e = d_off[gw + 1];
    float4 acc = make_float4(0.f, 0.f, 0.f, 0.f);
    const float4* hp = (const float4*)d_h;
    #pragma unroll 4
    for (int j = s; j < e; ++j) {
        int c = d_colp[j];
        float4 v = hp[(size_t)c * 32 + lane];
        acc.x += v.x; acc.y += v.y; acc.z += v.z; acc.w += v.w;
    }
    ((float4*)d_SA)[(size_t)gw * (KC / 4) + lane] = acc;
}

// ---------------- node GEMM: 128x128 tile, 256 thr, 8x8 acc, double-buffered ----------------
// mode 0: h = relu(A @ W + bias)
// mode 1: h += relu(((A @ W) * deginv + bias) * (gamma/sqrt(1+eps)) + beta)
__global__ void __launch_bounds__(256, 2) k_gemm(
    const float* __restrict__ A, int lda, int K,
    const float* __restrict__ W,
    const float* __restrict__ bias,
    const float* __restrict__ gam,
    const float* __restrict__ bet,
    int mode, int n)
{
    __shared__ float As[2][16][128];
    __shared__ float Bs[2][16][128];
    int tid = threadIdx.x;
    int tx = tid & 15;           // col group: cols tx*8 .. +7
    int ty = tid >> 4;           // row group: rows ty*8 .. +7
    int m0 = blockIdx.x * 128;

    // prefetch indices: 2 float4 of A, 2 float4 of B per thread per tile
    int am[2], ak[2], bk[2], bj[2];
    #pragma unroll
    for (int i = 0; i < 2; ++i) {
        int idx = tid + i * 256;
        am[i] = idx >> 2;        // 0..127
        ak[i] = (idx & 3) * 4;   // 0,4,8,12
        bk[i] = idx >> 5;        // 0..15
        bj[i] = (idx & 31) * 4;  // 0..124
    }

    float acc[8][8];
    #pragma unroll
    for (int r = 0; r < 8; ++r)
        #pragma unroll
        for (int c = 0; c < 8; ++c) acc[r][c] = 0.f;

    int tiles = (K + 15) >> 4;
    float4 pa[2], pb[2];

    // load tile 0
    #pragma unroll
    for (int i = 0; i < 2; ++i) {
        int gm = m0 + am[i], k = ak[i];
        pa[i] = make_float4(0.f, 0.f, 0.f, 0.f);
        if (gm < n && k < K) pa[i] = *(const float4*)(A + (size_t)gm * lda + k);
        int kb = bk[i];
        pb[i] = (kb < K) ? *(const float4*)(W + (size_t)kb * 128 + bj[i])
                         : make_float4(0.f, 0.f, 0.f, 0.f);
    }
    #pragma unroll
    for (int i = 0; i < 2; ++i) {
        As[0][ak[i] + 0][am[i]] = pa[i].x;
        As[0][ak[i] + 1][am[i]] = pa[i].y;
        As[0][ak[i] + 2][am[i]] = pa[i].z;
        As[0][ak[i] + 3][am[i]] = pa[i].w;
        *(float4*)&Bs[0][bk[i]][bj[i]] = pb[i];
    }
    __syncthreads();

    for (int t = 0; t < tiles; ++t) {
        int cur = t & 1;
        int k0n = (t + 1) << 4;
        if (t + 1 < tiles) {
            #pragma unroll
            for (int i = 0; i < 2; ++i) {
                int gm = m0 + am[i], k = k0n + ak[i];
                pa[i] = make_float4(0.f, 0.f, 0.f, 0.f);
                if (gm < n && k < K) pa[i] = *(const float4*)(A + (size_t)gm * lda + k);
                int kb = k0n + bk[i];
                pb[i] = (kb < K) ? *(const float4*)(W + (size_t)kb * 128 + bj[i])
                                 : make_float4(0.f, 0.f, 0.f, 0.f);
            }
        }
        #pragma unroll
        for (int kk = 0; kk < 16; ++kk) {
            float4 a0 = *(const float4*)&As[cur][kk][ty * 8];
            float4 a1 = *(const float4*)&As[cur][kk][ty * 8 + 4];
            float4 b0 = *(const float4*)&Bs[cur][kk][tx * 8];
            float4 b1 = *(const float4*)&Bs[cur][kk][tx * 8 + 4];
            const float* ap = (const float*)&a0;
            const float* bp = (const float*)&b0;
            #pragma unroll
            for (int r = 0; r < 8; ++r) {
                float av = (r < 4) ? ((const float*)&a0)[r] : ((const float*)&a1)[r - 4];
                acc[r][0] += av * b0.x; acc[r][1] += av * b0.y;
                acc[r][2] += av * b0.z; acc[r][3] += av * b0.w;
                acc[r][4] += av * b1.x; acc[r][5] += av * b1.y;
                acc[r][6] += av * b1.z; acc[r][7] += av * b1.w;
            }
            (void)ap; (void)bp;
        }
        if (t + 1 < tiles) {
            int nb = cur ^ 1;
            #pragma unroll
            for (int i = 0; i < 2; ++i) {
                As[nb][ak[i] + 0][am[i]] = pa[i].x;
                As[nb][ak[i] + 1][am[i]] = pa[i].y;
                As[nb][ak[i] + 2][am[i]] = pa[i].z;
                As[nb][ak[i] + 3][am[i]] = pa[i].w;
                *(float4*)&Bs[nb][bk[i]][bj[i]] = pb[i];
            }
        }
        __syncthreads();
    }

    // epilogue
    const float bnc = rsqrtf(1.0f + 1e-3f);
    float bv[8], gv[8], tv[8];
    #pragma unroll
    for (int c = 0; c < 8; ++c) {
        int j = tx * 8 + c;
        bv[c] = bias[j];
        if (mode == 1) { gv[c] = gam[j] * bnc; tv[c] = bet[j]; }
    }
    #pragma unroll
    for (int r = 0; r < 8; ++r) {
        int gm = m0 + ty * 8 + r;
        if (gm >= n) continue;
        float* hp = d_h + (size_t)gm * HD + tx * 8;
        if (mode == 0) {
            float4 o0, o1;
            o0.x = fmaxf(acc[r][0] + bv[0], 0.f); o0.y = fmaxf(acc[r][1] + bv[1], 0.f);
            o0.z = fmaxf(acc[r][2] + bv[2], 0.f); o0.w = fmaxf(acc[r][3] + bv[3], 0.f);
            o1.x = fmaxf(acc[r][4] + bv[4], 0.f); o1.y = fmaxf(acc[r][5] + bv[5], 0.f);
            o1.z = fmaxf(acc[r][6] + bv[6], 0.f); o1.w = fmaxf(acc[r][7] + bv[7], 0.f);
            *(float4*)hp = o0;
            *(float4*)(hp + 4) = o1;
        } else {
            float di = d_deginv[gm];
            float4 h0 = *(const float4*)hp;
            float4 h1 = *(const float4*)(hp + 4);
            float* h0p = (float*)&h0;
            float* h1p = (float*)&h1;
            #pragma unroll
            for (int c = 0; c < 8; ++c) {
                float v = acc[r][c] * di + bv[c];
                v = v * gv[c] + tv[c];
                v = fmaxf(v, 0.f);
                if (c < 4) h0p[c] += v; else h1p[c - 4] += v;
            }
            *(float4*)hp = h0;
            *(float4*)(hp + 4) = h1;
        }
    }
}

// ---------------- graph mean-pool ----------------
__global__ void k_pool(const int* __restrict__ bidx, int n) {
    int g = blockIdx.x, t = threadIdx.x;
    int lo, hi;
    { int a = 0, b = n; while (a < b) { int m = (a + b) >> 1; if (bidx[m] < g)     a = m + 1; else b = m; } lo = a; }
    { int a = 0, b = n; while (a < b) { int m = (a + b) >> 1; if (bidx[m] < g + 1) a = m + 1; else b = m; } hi = a; }
    float acc = 0.f;
    for (int i = lo; i < hi; ++i) acc += d_h[(size_t)i * HD + t];
    float inv = 1.0f / fmaxf((float)(hi - lo), 1.0f);
    d_gpool[g * HD + t] = acc * inv;
}

// ---------------- head ----------------
__global__ void k_head(const float* __restrict__ Wh, const float* __restrict__ bh,
                       const float* __restrict__ Wout, const float* __restrict__ bout,
                       float* __restrict__ out) {
    __shared__ float gs[128];
    __shared__ float red[4];
    int g = blockIdx.x, t = threadIdx.x;
    gs[t] = d_gpool[g * HD + t];
    __syncthreads();
    float acc = bh[t];
    #pragma unroll 8
    for (int k = 0; k < 128; ++k) acc += gs[k] * Wh[k * 128 + t];
    float hv = fmaxf(acc, 0.f);
    float p = hv * Wout[t];
    #pragma unroll
    for (int s = 16; s; s >>= 1) p += __shfl_down_sync(0xffffffffu, p, s);
    if ((t & 31) == 0) red[t >> 5] = p;
    __syncthreads();
    if (t == 0) out[g] = red[0] + red[1] + red[2] + red[3] + bout[0];
}

// ---------------- launch ----------------
extern "C" void kernel_launch(void* const* d_in, const int* in_sizes, int n_in,
                              void* d_out, int out_size) {
    const float* x     = (const float*)d_in[0];
    const int*   ei    = (const int*)  d_in[1];
    const float* ea    = (const float*)d_in[2];
    const int*   bidx  = (const int*)  d_in[3];
    const float* W_emb = (const float*)d_in[4];
    const float* b_emb = (const float*)d_in[5];
    const float* Wc    = (const float*)d_in[6];
    const float* bc    = (const float*)d_in[7];
    const float* gamma = (const float*)d_in[8];
    const float* beta  = (const float*)d_in[9];
    const float* Wh    = (const float*)d_in[10];
    const float* bh    = (const float*)d_in[11];
    const float* Wout  = (const float*)d_in[12];
    const float* bout  = (const float*)d_in[13];
    float* out = (float*)d_out;

    int n = in_sizes[0] / FN;
    int e = in_sizes[1] / 2;
    const int* row = ei;
    const int* col = ei + e;

    // CSR build
    k_zero   <<<(n + 255) / 256, 256>>>(n);
    k_hist   <<<(e + 255) / 256, 256>>>(row, e);
    k_scan   <<<1, 1024>>>(n);
    k_scatter<<<(e + 255) / 256, 256>>>(row, col, e);

    // layer-invariant edge-attr aggregation (cols 128..191 of d_SA)
    k_ea<<<(n * 32 + 255) / 256, 256>>>(ea, n);

    int gb = (n + 127) / 128;
    float* sa = nullptr;
    cudaGetSymbolAddress((void**)&sa, d_SA);

    // embedding: h = relu(x @ W_emb + b_emb)
    k_gemm<<<gb, 256>>>(x, FN, FN, W_emb, b_emb, nullptr, nullptr, 0, n);

    for (int l = 0; l < LAYERS; ++l) {
        k_spmm<<<(n * 32 + 255) / 256, 256>>>(n);
        k_gemm<<<gb, 256>>>(sa, KC, KC,
                            Wc + (size_t)l * KC * HD,
                            bc + (size_t)l * HD,
                            gamma + (size_t)l * HD,
                            beta + (size_t)l * HD,
                            1, n);
    }

    k_pool<<<NG, 128>>>(bidx, n);
    k_head<<<NG, 128>>>(Wh, bh, Wout, bout, out);
}